// round 1
// baseline (speedup 1.0000x reference)
#include <cuda_runtime.h>
#include <cuda_bf16.h>

#define N_SRC_C   100000
#define N_DST_C   50000
#define N_EDGES_C 800000
#define DD        64

// Scratch (device globals; no allocation allowed)
__device__ float g_sums[N_DST_C * DD];
__device__ float g_cnt[N_DST_C];

// ---------------------------------------------------------------------------
// Kernel 1: zero the scratch accumulators
// ---------------------------------------------------------------------------
__global__ void zero_kernel() {
    int i = blockIdx.x * blockDim.x + threadIdx.x;
    int stride = gridDim.x * blockDim.x;
    const int n4 = (N_DST_C * DD) / 4;
    float4 z = make_float4(0.f, 0.f, 0.f, 0.f);
    for (int j = i; j < n4; j += stride)
        reinterpret_cast<float4*>(g_sums)[j] = z;
    for (int j = i; j < N_DST_C; j += stride)
        g_cnt[j] = 0.f;
}

// ---------------------------------------------------------------------------
// Kernel 2: segmented edge aggregation.
// dst_idx is sorted, so a 64-thread group (one thread per feature column)
// walks 64 consecutive edges, accumulating in a register while dst stays the
// same and flushing with atomicAdd on change. Loads are batched 8 edges at a
// time for MLP.
// ---------------------------------------------------------------------------
__global__ void __launch_bounds__(256)
agg_kernel(const float* __restrict__ H_src,
           const int*   __restrict__ src_idx,
           const int*   __restrict__ dst_idx) {
    const int EPG = 64;                      // edges per 64-thread group
    int g  = blockIdx.x * 4 + (threadIdx.x >> 6);
    int c  = threadIdx.x & 63;               // feature column
    int e0 = g * EPG;                        // N_EDGES divisible by 64

    float acc = 0.f, run = 0.f;
    int   cur = -1;

    #pragma unroll 1
    for (int base = e0; base < e0 + EPG; base += 8) {
        int   s[8], d[8];
        float v[8];
        #pragma unroll
        for (int j = 0; j < 8; j++) {
            s[j] = __ldg(src_idx + base + j);
            d[j] = __ldg(dst_idx + base + j);
        }
        #pragma unroll
        for (int j = 0; j < 8; j++)
            v[j] = __ldg(H_src + (size_t)s[j] * DD + c);
        #pragma unroll
        for (int j = 0; j < 8; j++) {
            if (d[j] != cur) {
                if (cur >= 0) {
                    atomicAdd(g_sums + (size_t)cur * DD + c, acc);
                    if (c == 0) atomicAdd(g_cnt + cur, run);
                }
                cur = d[j];
                acc = 0.f;
                run = 0.f;
            }
            acc += v[j];
            run += 1.f;
        }
    }
    if (cur >= 0) {
        atomicAdd(g_sums + (size_t)cur * DD + c, acc);
        if (c == 0) atomicAdd(g_cnt + cur, run);
    }
}

// ---------------------------------------------------------------------------
// Kernel 3: h_neigh = 0.9*HBar + 0.1 * sums/max(cnt,1), written to out2.
// ---------------------------------------------------------------------------
__global__ void neigh_kernel(const float* __restrict__ HBar,
                             float* __restrict__ out2) {
    int i = blockIdx.x * blockDim.x + threadIdx.x;   // float4 index
    const int total4 = N_DST_C * DD / 4;
    if (i >= total4) return;
    int row = i >> 4;                                // (i*4) / 64
    float inv = 0.1f / fmaxf(g_cnt[row], 1.f);
    float4 s  = reinterpret_cast<const float4*>(g_sums)[i];
    float4 hb = __ldg(reinterpret_cast<const float4*>(HBar) + i);
    float4 o;
    o.x = 0.9f * hb.x + s.x * inv;
    o.y = 0.9f * hb.y + s.y * inv;
    o.z = 0.9f * hb.z + s.z * inv;
    o.w = 0.9f * hb.w + s.w * inv;
    reinterpret_cast<float4*>(out2)[i] = o;
}

// ---------------------------------------------------------------------------
// Kernel 4: h = relu([H_dst, h_neigh] @ W^T + b)
// Block: 256 threads, 64 rows x 64 output cols, 4x4 register tile per thread.
// W (64x128) transposed into shared, k-major, stride 66 with a +1 offset for
// j>=32 -> conflict-free scalar reads. x read via L1 (broadcast across 16
// threads with the same ty).
// ---------------------------------------------------------------------------
__global__ void __launch_bounds__(256)
gemm_kernel(const float* __restrict__ H_dst,
            const float* __restrict__ out2,
            const float* __restrict__ W,
            const float* __restrict__ b,
            float* __restrict__ out) {
    __shared__ float ws[128 * 66 + 4];

    int t = threadIdx.x;
    // Transpose W into shared: WS(k, j) = ws[k*66 + j + (j>>5)]
    for (int i = t; i < 64 * 128; i += 256) {
        int j = i >> 7;
        int k = i & 127;
        ws[k * 66 + j + (j >> 5)] = __ldg(W + i);
    }
    __syncthreads();

    int tx = t & 15;
    int ty = t >> 4;
    int j0 = tx * 4;
    int r0 = (blockIdx.x << 6) + ty * 4;

    const float* xr[4];
    const float* yr[4];
    #pragma unroll
    for (int m = 0; m < 4; m++) {
        int row = min(r0 + m, N_DST_C - 1);
        xr[m] = H_dst + (size_t)row * DD;
        yr[m] = out2  + (size_t)row * DD;
    }

    float acc[4][4];
    #pragma unroll
    for (int r = 0; r < 4; r++)
        #pragma unroll
        for (int j = 0; j < 4; j++)
            acc[r][j] = 0.f;

    const float* wp = ws + j0 + (j0 >> 5);

    #pragma unroll 4
    for (int k = 0; k < 64; k++) {
        float wa[4], xa[4];
        #pragma unroll
        for (int m = 0; m < 4; m++) wa[m] = wp[k * 66 + m];
        #pragma unroll
        for (int m = 0; m < 4; m++) xa[m] = __ldg(xr[m] + k);
        #pragma unroll
        for (int r = 0; r < 4; r++)
            #pragma unroll
            for (int j = 0; j < 4; j++)
                acc[r][j] += xa[r] * wa[j];
    }
    #pragma unroll 4
    for (int k = 0; k < 64; k++) {
        float wa[4], xa[4];
        #pragma unroll
        for (int m = 0; m < 4; m++) wa[m] = wp[(k + 64) * 66 + m];
        #pragma unroll
        for (int m = 0; m < 4; m++) xa[m] = __ldg(yr[m] + k);
        #pragma unroll
        for (int r = 0; r < 4; r++)
            #pragma unroll
            for (int j = 0; j < 4; j++)
                acc[r][j] += xa[r] * wa[j];
    }

    float bb[4];
    #pragma unroll
    for (int j = 0; j < 4; j++) bb[j] = __ldg(b + j0 + j);

    #pragma unroll
    for (int m = 0; m < 4; m++) {
        int row = r0 + m;
        if (row < N_DST_C) {
            float4 o;
            o.x = fmaxf(acc[m][0] + bb[0], 0.f);
            o.y = fmaxf(acc[m][1] + bb[1], 0.f);
            o.z = fmaxf(acc[m][2] + bb[2], 0.f);
            o.w = fmaxf(acc[m][3] + bb[3], 0.f);
            *reinterpret_cast<float4*>(out + (size_t)row * DD + j0) = o;
        }
    }
}

// ---------------------------------------------------------------------------
// Launch
// ---------------------------------------------------------------------------
extern "C" void kernel_launch(void* const* d_in, const int* in_sizes, int n_in,
                              void* d_out, int out_size) {
    const float* H_src   = (const float*)d_in[0];
    const float* H_dst   = (const float*)d_in[1];
    const float* HBar    = (const float*)d_in[2];
    const int*   src_idx = (const int*)  d_in[3];
    const int*   dst_idx = (const int*)  d_in[4];
    const float* W       = (const float*)d_in[5];
    const float* b       = (const float*)d_in[6];

    float* out  = (float*)d_out;                    // h:       [N_DST, 64]
    float* out2 = out + (size_t)N_DST_C * DD;       // h_neigh: [N_DST, 64]

    zero_kernel<<<256, 256>>>();
    agg_kernel<<<N_EDGES_C / 64 / 4, 256>>>(H_src, src_idx, dst_idx);
    neigh_kernel<<<(N_DST_C * DD / 4 + 255) / 256, 256>>>(HBar, out2);
    gemm_kernel<<<(N_DST_C + 63) / 64, 256>>>(H_dst, out2, W, b, out);
}

// round 4
// speedup vs baseline: 1.3404x; 1.3404x over previous
#include <cuda_runtime.h>
#include <cuda_bf16.h>

#define N_SRC_C   100000
#define N_DST_C   50000
#define N_EDGES_C 800000
#define DD        64

// Scratch (device globals; no allocation allowed)
__device__ float g_sums[N_DST_C * DD];
__device__ float g_cnt[N_DST_C];
__device__ float g_Wt[128 * 64];     // W transposed: Wt[k][j] = W[j][k]

// Packed f32x2 helpers (sm_103a)
#define FMA2(d, a, bb) \
    asm("fma.rn.f32x2 %0, %1, %2, %3;" : "=l"(d) : "l"(a), "l"(bb), "l"(d))
#define PACKDUP(o, x) \
    asm("mov.b64 %0, {%1, %1};" : "=l"(o) : "f"(x))

// ---------------------------------------------------------------------------
// Kernel 1: zero scratch + transpose W into g_Wt
// ---------------------------------------------------------------------------
__global__ void prep_kernel(const float* __restrict__ W) {
    int i = blockIdx.x * blockDim.x + threadIdx.x;
    int stride = gridDim.x * blockDim.x;
    const int n4 = (N_DST_C * DD) / 4;
    float4 z = make_float4(0.f, 0.f, 0.f, 0.f);
    for (int j = i; j < n4; j += stride)
        reinterpret_cast<float4*>(g_sums)[j] = z;
    for (int j = i; j < N_DST_C; j += stride)
        g_cnt[j] = 0.f;
    // Coalesced READ of W (consecutive i -> consecutive W addr), strided write.
    // i = jj*128 + k  ->  Wt[k*64 + jj] = W[i]
    for (int j = i; j < 128 * 64; j += stride) {
        int jj = j >> 7;        // output row of W   (0..63)
        int k  = j & 127;       // input column      (0..127)
        g_Wt[k * 64 + jj] = __ldg(W + j);
    }
}

// ---------------------------------------------------------------------------
// Kernel 2: segmented edge aggregation. 16-thread groups, float4 per thread.
// dst_idx sorted -> register accumulation per segment, atomic flush on change.
// ---------------------------------------------------------------------------
__global__ void __launch_bounds__(256)
agg_kernel(const float* __restrict__ H_src,
           const int*   __restrict__ src_idx,
           const int*   __restrict__ dst_idx) {
    const int EPG = 64;                         // edges per 16-thread group
    int g = blockIdx.x * 16 + (threadIdx.x >> 4);
    if (g >= N_EDGES_C / EPG) return;
    int c4 = threadIdx.x & 15;                  // float4 column index
    int e0 = g * EPG;

    float4 acc = make_float4(0.f, 0.f, 0.f, 0.f);
    float run = 0.f;
    int   cur = -1;

    #pragma unroll 1
    for (int base = e0; base < e0 + EPG; base += 8) {
        int4 s0 = __ldg((const int4*)(src_idx + base));
        int4 s1 = __ldg((const int4*)(src_idx + base + 4));
        int4 d0 = __ldg((const int4*)(dst_idx + base));
        int4 d1 = __ldg((const int4*)(dst_idx + base + 4));
        int s[8] = { s0.x, s0.y, s0.z, s0.w, s1.x, s1.y, s1.z, s1.w };
        int d[8] = { d0.x, d0.y, d0.z, d0.w, d1.x, d1.y, d1.z, d1.w };
        float4 v[8];
        #pragma unroll
        for (int j = 0; j < 8; j++)
            v[j] = __ldg((const float4*)(H_src + (size_t)s[j] * DD) + c4);
        #pragma unroll
        for (int j = 0; j < 8; j++) {
            if (d[j] != cur) {
                if (cur >= 0) {
                    float* p = g_sums + (size_t)cur * DD + c4 * 4;
                    atomicAdd(p + 0, acc.x);
                    atomicAdd(p + 1, acc.y);
                    atomicAdd(p + 2, acc.z);
                    atomicAdd(p + 3, acc.w);
                    if (c4 == 0) atomicAdd(g_cnt + cur, run);
                }
                cur = d[j];
                acc = make_float4(0.f, 0.f, 0.f, 0.f);
                run = 0.f;
            }
            acc.x += v[j].x; acc.y += v[j].y;
            acc.z += v[j].z; acc.w += v[j].w;
            run += 1.f;
        }
    }
    if (cur >= 0) {
        float* p = g_sums + (size_t)cur * DD + c4 * 4;
        atomicAdd(p + 0, acc.x);
        atomicAdd(p + 1, acc.y);
        atomicAdd(p + 2, acc.z);
        atomicAdd(p + 3, acc.w);
        if (c4 == 0) atomicAdd(g_cnt + cur, run);
    }
}

// ---------------------------------------------------------------------------
// Kernel 3: h_neigh = 0.9*HBar + 0.1 * sums/max(cnt,1), written to out2.
// ---------------------------------------------------------------------------
__global__ void neigh_kernel(const float* __restrict__ HBar,
                             float* __restrict__ out2) {
    int i = blockIdx.x * blockDim.x + threadIdx.x;   // float4 index
    const int total4 = N_DST_C * DD / 4;
    if (i >= total4) return;
    int row = i >> 4;
    float inv = 0.1f / fmaxf(g_cnt[row], 1.f);
    float4 s  = reinterpret_cast<const float4*>(g_sums)[i];
    float4 hb = __ldg(reinterpret_cast<const float4*>(HBar) + i);
    float4 o;
    o.x = 0.9f * hb.x + s.x * inv;
    o.y = 0.9f * hb.y + s.y * inv;
    o.z = 0.9f * hb.z + s.z * inv;
    o.w = 0.9f * hb.w + s.w * inv;
    reinterpret_cast<float4*>(out2)[i] = o;
}

// ---------------------------------------------------------------------------
// Kernel 4: h = relu([H_dst, h_neigh] @ W^T + b)
// 256 threads, 64 rows x 64 cols, 4x4 tile per thread, packed f32x2 FMA.
// W pre-transposed in g_Wt (k-major), linear-copied to shared (conflict-free),
// read as LDS.128. x rows read as LDG.128 (4 k per load).
// ---------------------------------------------------------------------------
__global__ void __launch_bounds__(256)
gemm_kernel(const float* __restrict__ H_dst,
            const float* __restrict__ out2,
            const float* __restrict__ b,
            float* __restrict__ out) {
    __shared__ float ws[128 * 64];

    int t = threadIdx.x;
    // Linear float4 copy of pre-transposed W: fully coalesced, conflict-free.
    #pragma unroll
    for (int i = 0; i < 8; i++) {
        int idx = t + i * 256;
        reinterpret_cast<float4*>(ws)[idx] =
            __ldg(reinterpret_cast<const float4*>(g_Wt) + idx);
    }
    __syncthreads();

    int tx = t & 15;
    int ty = t >> 4;
    int j0 = tx * 4;
    int r0 = (blockIdx.x << 6) + ty * 4;

    const float* xr[4];
    const float* yr[4];
    #pragma unroll
    for (int m = 0; m < 4; m++) {
        int row = min(r0 + m, N_DST_C - 1);
        xr[m] = H_dst + (size_t)row * DD;
        yr[m] = out2  + (size_t)row * DD;
    }

    unsigned long long acc[4][2];
    #pragma unroll
    for (int r = 0; r < 4; r++) { acc[r][0] = 0ull; acc[r][1] = 0ull; }

    // First half: k = 0..63 over H_dst
    #pragma unroll 4
    for (int k = 0; k < 64; k += 4) {
        float4 xa[4];
        #pragma unroll
        for (int m = 0; m < 4; m++)
            xa[m] = __ldg((const float4*)(xr[m] + k));
        #pragma unroll
        for (int kk = 0; kk < 4; kk++) {
            ulonglong2 w2 = *reinterpret_cast<const ulonglong2*>(
                ws + (k + kk) * 64 + j0);
            #pragma unroll
            for (int r = 0; r < 4; r++) {
                float xs = reinterpret_cast<const float*>(&xa[r])[kk];
                unsigned long long xx;
                PACKDUP(xx, xs);
                FMA2(acc[r][0], xx, w2.x);
                FMA2(acc[r][1], xx, w2.y);
            }
        }
    }
    // Second half: k = 64..127 over h_neigh (out2)
    #pragma unroll 4
    for (int k = 0; k < 64; k += 4) {
        float4 xa[4];
        #pragma unroll
        for (int m = 0; m < 4; m++)
            xa[m] = __ldg((const float4*)(yr[m] + k));
        #pragma unroll
        for (int kk = 0; kk < 4; kk++) {
            ulonglong2 w2 = *reinterpret_cast<const ulonglong2*>(
                ws + (k + 64 + kk) * 64 + j0);
            #pragma unroll
            for (int r = 0; r < 4; r++) {
                float xs = reinterpret_cast<const float*>(&xa[r])[kk];
                unsigned long long xx;
                PACKDUP(xx, xs);
                FMA2(acc[r][0], xx, w2.x);
                FMA2(acc[r][1], xx, w2.y);
            }
        }
    }

    float bb[4];
    #pragma unroll
    for (int j = 0; j < 4; j++) bb[j] = __ldg(b + j0 + j);

    #pragma unroll
    for (int m = 0; m < 4; m++) {
        int row = r0 + m;
        if (row < N_DST_C) {
            float2 p0 = *reinterpret_cast<float2*>(&acc[m][0]);
            float2 p1 = *reinterpret_cast<float2*>(&acc[m][1]);
            float4 o;
            o.x = fmaxf(p0.x + bb[0], 0.f);
            o.y = fmaxf(p0.y + bb[1], 0.f);
            o.z = fmaxf(p1.x + bb[2], 0.f);
            o.w = fmaxf(p1.y + bb[3], 0.f);
            *reinterpret_cast<float4*>(out + (size_t)row * DD + j0) = o;
        }
    }
}

// ---------------------------------------------------------------------------
// Launch
// ---------------------------------------------------------------------------
extern "C" void kernel_launch(void* const* d_in, const int* in_sizes, int n_in,
                              void* d_out, int out_size) {
    const float* H_src   = (const float*)d_in[0];
    const float* H_dst   = (const float*)d_in[1];
    const float* HBar    = (const float*)d_in[2];
    const int*   src_idx = (const int*)  d_in[3];
    const int*   dst_idx = (const int*)  d_in[4];
    const float* W       = (const float*)d_in[5];
    const float* b       = (const float*)d_in[6];

    float* out  = (float*)d_out;                    // h:       [N_DST, 64]
    float* out2 = out + (size_t)N_DST_C * DD;       // h_neigh: [N_DST, 64]

    prep_kernel<<<256, 256>>>(W);
    agg_kernel<<<(N_EDGES_C / 64 + 15) / 16, 256>>>(H_src, src_idx, dst_idx);
    neigh_kernel<<<(N_DST_C * DD / 4 + 255) / 256, 256>>>(HBar, out2);
    gemm_kernel<<<(N_DST_C + 63) / 64, 256>>>(H_dst, out2, b, out);
}